// round 11
// baseline (speedup 1.0000x reference)
#include <cuda_runtime.h>
#include <cuda_fp16.h>
#include <stdint.h>
#include <math.h>

typedef uint32_t u32; typedef uint64_t u64; typedef unsigned short u16;

#define N_PTS 262144
#define TOTB 4640

// weight blocks in B-fragment order (fp16): block b = 256B: lane l at [b*32+l]
__device__ __align__(16) u64 g_w[TOTB * 32];
__device__ float g_dcol[256];

// seg block offsets (layout: Win | Wh0..Wh4 | H4PE | Wh5 | Wh6 | Wout | Wr1 | Wr1de)
#define SEG_WIN  0
#define SEG_H0   128
#define SEG_H4PE 2688
#define SEG_H5   2816
#define SEG_H6   3328
#define SEG_OUT  3840
#define SEG_R1   4352
#define SEG_R1DE 4608

__device__ __forceinline__ u32 f2h(float f) {
    return (u32)__half_as_ushort(__float2half_rn(f));
}
__device__ __forceinline__ float h2f(u32 h) {
    return __half2float(__ushort_as_half((u16)h));
}
__device__ __forceinline__ u32 s2u(const void* p) {
    u32 a;
    asm("{ .reg .u64 t; cvta.to.shared.u64 t, %1; cvt.u32.u64 %0, t; }" : "=r"(a) : "l"(p));
    return a;
}

#define LDMX4(R, addr) \
    asm volatile("ldmatrix.sync.aligned.m8n8.x4.shared.b16 {%0,%1,%2,%3}, [%4];" \
        : "=r"((R)[0]), "=r"((R)[1]), "=r"((R)[2]), "=r"((R)[3]) : "r"(addr))

#define MMA(D, A, b0, b1) \
    asm volatile("mma.sync.aligned.m16n8k16.row.col.f32.f16.f16.f32 " \
        "{%0,%1,%2,%3},{%4,%5,%6,%7},{%8,%9},{%0,%1,%2,%3};" \
        : "+f"((D)[0]), "+f"((D)[1]), "+f"((D)[2]), "+f"((D)[3]) \
        : "r"((A)[0]), "r"((A)[1]), "r"((A)[2]), "r"((A)[3]), "r"(b0), "r"(b1))

// ---------- SMEM layout (bytes) ----------
// A halves: half0 @0, half1 @33792; within a half: tile P @+0, tile Q @+16896
#define A_HALF1 33792
#define A_TILE  16896
#define O_PE   67584   // P @+0, Q @+4608 (32 rows x 72 cols fp16)
#define O_DE   76800   // P @+0, Q @+2560 (32 rows x 40 cols fp16)
#define O_BIAS 81920   // 2432 floats
#define O_DCOL 91648
#define O_WR2  92672
#define SMEM_TOTAL 94208

// ---------- prep kernel (unchanged weight layout) ----------
struct Seg { const float* src; int rs, kv, nv, NT, start; };
struct PrepP { Seg seg[12]; const float* Wout; };

__global__ void prep_kernel(PrepP pp) {
    int b = blockIdx.x * 8 + (threadIdx.x >> 5);
    int l = threadIdx.x & 31;
    if (blockIdx.x == 0) g_dcol[threadIdx.x] = pp.Wout[threadIdx.x * 257 + 256];
    int si = 0;
#pragma unroll
    for (int i = 1; i < 12; i++) if (b >= pp.seg[i].start) si = i;
    Seg sg = pp.seg[si];
    int rel = b - sg.start;
    int s = rel / sg.NT, tg = rel % sg.NT;
    int n = tg * 8 + (l >> 2);
    u64 hv = 0;
#pragma unroll
    for (int idx = 0; idx < 4; idx++) {
        int r = idx >> 1, j = idx & 1;
        int k = s * 16 + (l & 3) * 2 + r * 8 + j;
        float w = (k < sg.kv && n < sg.nv) ? sg.src[(size_t)k * sg.rs + n] : 0.f;
        hv |= (u64)f2h(w) << (16 * idx);
    }
    g_w[(size_t)b * 32 + l] = hv;
}

// ---------- main kernel ----------
struct Params {
    const float *pos, *dir, *bout, *wr2, *br2;
    const float* bias[10];
    float* out;
};

// MMA over one K-segment, M=32 tile (1 m16-tile per warp).
template<int NTW>
__device__ __forceinline__ void run_seg(float (&acc)[NTW][4], u32 a_base,
    int S, int NT, const u64* __restrict__ wseg, int wn, int l)
{
    for (int s = 0; s < S; s++) {
        u32 ah[4];
        LDMX4(ah, a_base + s * 32);
        const u64* blk = wseg + (size_t)(s * NT + wn * NTW) * 32 + l;
        u64 wh[NTW];
#pragma unroll
        for (int t = 0; t < NTW; t++) wh[t] = blk[t * 32];
#pragma unroll
        for (int t = 0; t < NTW; t++) {
            u32 h0 = (u32)wh[t], h1 = (u32)(wh[t] >> 32);
            MMA(acc[t], ah, h0, h1);
        }
    }
}

template<int NTW>
__device__ __forceinline__ void epilogue(float (&acc)[NTW][4], u16* HI,
    const float* sbias, bool relu, int wm, int wn, int l)
{
    int cb = wn * NTW * 8 + (l & 3) * 2;
    int rb = wm * 16 + (l >> 2);
#pragma unroll
    for (int t = 0; t < NTW; t++)
#pragma unroll
        for (int h = 0; h < 2; h++) {
            int r = rb + h * 8, c = cb + t * 8;
            float v0 = acc[t][2 * h]     + sbias[c];
            float v1 = acc[t][2 * h + 1] + sbias[c + 1];
            if (relu) { v0 = fmaxf(v0, 0.f); v1 = fmaxf(v1, 0.f); }
            *(u32*)&HI[r * 264 + c] = f2h(v0) | (f2h(v1) << 16);
        }
}

__global__ void __launch_bounds__(256, 2) nerf_mma(Params p)
{
    extern __shared__ char sm[];
    float* sball = (float*)(sm + O_BIAS);
    float* sdcol = (float*)(sm + O_DCOL);
    float* swr2  = (float*)(sm + O_WR2);
    float* sred  = (float*)(sm + O_PE);   // scratch (PE dead after layer 4)

    const int tid = threadIdx.x;
    const int l = tid & 31, wid = tid >> 5;
    const int wm = wid >> 2, wn = wid & 3;   // wm: 16-row group, wn: 64-col group

#pragma unroll
    for (int L = 0; L < 9; L++) sball[L * 256 + tid] = p.bias[L][tid];
    if (tid < 128) sball[2304 + tid] = p.bias[9][tid];
    sdcol[tid] = g_dcol[tid];
    for (int i = tid; i < 384; i += 256) swr2[i] = p.wr2[i];

    // posenc (64 points; tile = tid>>5, row = tid&31)
    if (tid < 64) {
        const int tq = tid >> 5, m = tid & 31, pt = blockIdx.x * 64 + tid;
        u16* PHI = (u16*)(sm + O_PE + tq * 4608);
        u16* DHI = (u16*)(sm + O_DE + tq * 2560);
#define STP(H, STRD, COL, V) (H)[m * STRD + (COL)] = (u16)f2h(V)
        for (int d = 0; d < 3; d++) {
            float x = p.pos[pt * 3 + d];
            STP(PHI, 72, d, x);
            float f = 1.f;
#pragma unroll
            for (int q = 0; q < 10; q++) {
                float s, c; sincosf(x * f, &s, &c);
                STP(PHI, 72, 3 + 6 * q + d, s);
                STP(PHI, 72, 3 + 6 * q + 3 + d, c);
                f *= 2.f;
            }
            float y = p.dir[pt * 3 + d];
            STP(DHI, 40, d, y);
            f = 1.f;
#pragma unroll
            for (int q = 0; q < 4; q++) {
                float s, c; sincosf(y * f, &s, &c);
                STP(DHI, 40, 3 + 6 * q + d, s);
                STP(DHI, 40, 3 + 6 * q + 3 + d, c);
                f *= 2.f;
            }
        }
        STP(PHI, 72, 63, 0.f);
        for (int k = 27; k < 32; k++) STP(DHI, 40, k, 0.f);
#undef STP
    }
    __syncthreads();

    float acc[8][4];
#define ZACC() do { _Pragma("unroll") for (int _b = 0; _b < 8; _b++) \
    _Pragma("unroll") for (int _c = 0; _c < 4; _c++) acc[_b][_c] = 0.f; } while (0)
    const u32 lane_a  = (u32)((wm * 16 + (l & 15)) * 528 + (l >> 4) * 16);
    const u32 lane_pe = (u32)((wm * 16 + (l & 15)) * 144 + (l >> 4) * 16);
    const u32 lane_de = (u32)((wm * 16 + (l & 15)) * 80  + (l >> 4) * 16);
    const u32 sb = s2u(sm);
#define AB(tq)  (sb + cur + (u32)(tq) * A_TILE + lane_a)
#define PEB(tq) (sb + O_PE + (u32)(tq) * 4608 + lane_pe)
#define DEB(tq) (sb + O_DE + (u32)(tq) * 2560 + lane_de)

    u32 cur = 0, nxt = A_HALF1;

    // layer 0 (pe -> h); interleaved tiles, one sync per layer
#pragma unroll
    for (int tq = 0; tq < 2; tq++) {
        ZACC();
        run_seg<8>(acc, PEB(tq), 4, 32, g_w + (size_t)SEG_WIN * 32, wn, l);
        epilogue<8>(acc, (u16*)(sm + nxt + tq * A_TILE), sball, true, wm, wn, l);
    }
    __syncthreads();
    { u32 t = cur; cur = nxt; nxt = t; }

    // hidden layers (Wh5/Wh6 live AFTER the H4PE segment — explicit starts)
    for (int i = 0; i < 7; i++) {
        const int seg_start = (i < 5) ? (SEG_H0 + i * 512) : (SEG_H5 + (i - 5) * 512);
#pragma unroll
        for (int tq = 0; tq < 2; tq++) {
            ZACC();
            run_seg<8>(acc, AB(tq), 16, 32, g_w + (size_t)seg_start * 32, wn, l);
            if (i == 4)
                run_seg<8>(acc, PEB(tq), 4, 32, g_w + (size_t)SEG_H4PE * 32, wn, l);
            epilogue<8>(acc, (u16*)(sm + nxt + tq * A_TILE), sball + 256 * (1 + i), true, wm, wn, l);
        }
        __syncthreads();
        u32 t = cur; cur = nxt; nxt = t;
    }

    // density partials from h_final (4 threads/point), overlapped with out MMA
    {
        const int q = tid >> 6, m = tid & 63;
        float dsum = 0.f;
        const u64* arow = (const u64*)((u16*)(sm + cur + (m >> 5) * A_TILE) + (m & 31) * 264 + q * 64);
        const float* dc = sdcol + q * 64;
#pragma unroll
        for (int kb = 0; kb < 16; kb++) {
            u64 v = arow[kb];
            dsum += h2f((u32)(v      ) & 0xFFFF) * dc[kb * 4 + 0];
            dsum += h2f((u32)(v >> 16) & 0xFFFF) * dc[kb * 4 + 1];
            dsum += h2f((u32)(v >> 32) & 0xFFFF) * dc[kb * 4 + 2];
            dsum += h2f((u32)(v >> 48)         ) * dc[kb * 4 + 3];
        }
        sred[tid] = dsum;
    }
    // out layer (features, no relu)
#pragma unroll
    for (int tq = 0; tq < 2; tq++) {
        ZACC();
        run_seg<8>(acc, AB(tq), 16, 32, g_w + (size_t)SEG_OUT * 32, wn, l);
        epilogue<8>(acc, (u16*)(sm + nxt + tq * A_TILE), sball + 256 * 8, false, wm, wn, l);
    }
    __syncthreads();
    { u32 t = cur; cur = nxt; nxt = t; }
    if (tid < 64)
        p.out[3 * N_PTS + blockIdx.x * 64 + tid] =
            fmaxf(sred[tid] + sred[64 + tid] + sred[128 + tid] + sred[192 + tid]
                  + p.bout[256], 0.f);

    // r1: [features, de] @ Wr1, relu, N=128
    {
        float a4[4][4];
#pragma unroll
        for (int tq = 0; tq < 2; tq++) {
#pragma unroll
            for (int b = 0; b < 4; b++)
#pragma unroll
                for (int c = 0; c < 4; c++) a4[b][c] = 0.f;
            run_seg<4>(a4, AB(tq), 16, 16, g_w + (size_t)SEG_R1 * 32, wn, l);
            run_seg<4>(a4, DEB(tq), 2, 16, g_w + (size_t)SEG_R1DE * 32, wn, l);
            epilogue<4>(a4, (u16*)(sm + nxt + tq * A_TILE), sball + 2304, true, wm, wn, l);
        }
        __syncthreads();
        u32 t = cur; cur = nxt; nxt = t;
    }

    // r2 + sigmoid: 4 threads/point over 32-col quarters, SMEM reduce
    {
        const int q = tid >> 6, m = tid & 63;
        float r0 = 0.f, r1 = 0.f, r2 = 0.f;
        const u64* arow = (const u64*)((u16*)(sm + cur + (m >> 5) * A_TILE) + (m & 31) * 264 + q * 32);
#pragma unroll
        for (int kb = 0; kb < 8; kb++) {
            u64 v = arow[kb];
#pragma unroll
            for (int j = 0; j < 4; j++) {
                float hv = h2f((u32)(v >> (16 * j)) & 0xFFFF);
                const float* w = swr2 + (q * 32 + kb * 4 + j) * 3;
                r0 += hv * w[0]; r1 += hv * w[1]; r2 += hv * w[2];
            }
        }
        sred[tid] = r0; sred[256 + tid] = r1; sred[512 + tid] = r2;
    }
    __syncthreads();
    if (tid < 64) {
        const int pt = blockIdx.x * 64 + tid;
        float r0 = sred[tid] + sred[64 + tid] + sred[128 + tid] + sred[192 + tid] + p.br2[0];
        float r1 = sred[256 + tid] + sred[320 + tid] + sred[384 + tid] + sred[448 + tid] + p.br2[1];
        float r2 = sred[512 + tid] + sred[576 + tid] + sred[640 + tid] + sred[704 + tid] + p.br2[2];
        p.out[pt * 3 + 0] = 1.f / (1.f + expf(-r0));
        p.out[pt * 3 + 1] = 1.f / (1.f + expf(-r1));
        p.out[pt * 3 + 2] = 1.f / (1.f + expf(-r2));
    }
}

// ---------- host ----------
extern "C" void kernel_launch(void* const* d_in, const int* in_sizes, int n_in,
                              void* d_out, int out_size)
{
    const float* pos  = (const float*)d_in[0];
    const float* dir  = (const float*)d_in[1];
    const float* Win  = (const float*)d_in[2];
    const float* bin  = (const float*)d_in[3];
    const float* Wh[7]; const float* bh[7];
    for (int i = 0; i < 7; i++) { Wh[i] = (const float*)d_in[4 + 2 * i]; bh[i] = (const float*)d_in[5 + 2 * i]; }
    const float* Wout = (const float*)d_in[18];
    const float* bout = (const float*)d_in[19];
    const float* Wr1  = (const float*)d_in[20];
    const float* br1  = (const float*)d_in[21];
    const float* Wr2  = (const float*)d_in[22];
    const float* br2  = (const float*)d_in[23];

    static PrepP pp;
    pp.seg[0]  = { Win,               256, 63,  256, 32, SEG_WIN };
    for (int i = 0; i < 5; i++)
        pp.seg[1 + i] = { Wh[i],      256, 256, 256, 32, SEG_H0 + i * 512 };
    pp.seg[6]  = { Wh[4] + 256 * 256, 256, 63,  256, 32, SEG_H4PE };
    pp.seg[7]  = { Wh[5],             256, 256, 256, 32, SEG_H5 };
    pp.seg[8]  = { Wh[6],             256, 256, 256, 32, SEG_H6 };
    pp.seg[9]  = { Wout,              257, 256, 256, 32, SEG_OUT };
    pp.seg[10] = { Wr1,               128, 256, 128, 16, SEG_R1 };
    pp.seg[11] = { Wr1 + 256 * 128,   128, 27,  128, 16, SEG_R1DE };
    pp.Wout = Wout;

    static Params p;
    p.pos = pos; p.dir = dir; p.bout = bout; p.wr2 = Wr2; p.br2 = br2;
    p.bias[0] = bin;
    for (int i = 0; i < 7; i++) p.bias[1 + i] = bh[i];
    p.bias[8] = bout; p.bias[9] = br1;
    p.out = (float*)d_out;

    prep_kernel<<<TOTB / 8, 256>>>(pp);
    cudaFuncSetAttribute(nerf_mma, cudaFuncAttributeMaxDynamicSharedMemorySize, SMEM_TOTAL);
    nerf_mma<<<N_PTS / 64, 256, SMEM_TOTAL>>>(p);
}

// round 12
// speedup vs baseline: 1.3144x; 1.3144x over previous
#include <cuda_runtime.h>
#include <cuda_fp16.h>
#include <stdint.h>
#include <math.h>

typedef uint32_t u32; typedef uint64_t u64; typedef unsigned short u16;

#define N_PTS 262144
#define TOTB 4640

// weight blocks, PAIRED fragment order: for even b, lanes hold
// [ (b>>1)*64 + 2l ] = block b, [ +1 ] = block b+1  (16B/lane -> LDG.128)
__device__ __align__(16) u64 g_w[TOTB * 32];
__device__ float g_dcol[256];

// seg block offsets (layout: Win | Wh0..Wh4 | H4PE | Wh5 | Wh6 | Wout | Wr1 | Wr1de)
#define SEG_WIN  0
#define SEG_H0   128
#define SEG_H4PE 2688
#define SEG_H5   2816
#define SEG_H6   3328
#define SEG_OUT  3840
#define SEG_R1   4352
#define SEG_R1DE 4608

__device__ __forceinline__ u32 f2h(float f) {
    return (u32)__half_as_ushort(__float2half_rn(f));
}
__device__ __forceinline__ float h2f(u32 h) {
    return __half2float(__ushort_as_half((u16)h));
}
__device__ __forceinline__ u32 s2u(const void* p) {
    u32 a;
    asm("{ .reg .u64 t; cvta.to.shared.u64 t, %1; cvt.u32.u64 %0, t; }" : "=r"(a) : "l"(p));
    return a;
}

#define LDMX4(R, addr) \
    asm volatile("ldmatrix.sync.aligned.m8n8.x4.shared.b16 {%0,%1,%2,%3}, [%4];" \
        : "=r"((R)[0]), "=r"((R)[1]), "=r"((R)[2]), "=r"((R)[3]) : "r"(addr))

#define MMA(D, A, b0, b1) \
    asm volatile("mma.sync.aligned.m16n8k16.row.col.f32.f16.f16.f32 " \
        "{%0,%1,%2,%3},{%4,%5,%6,%7},{%8,%9},{%0,%1,%2,%3};" \
        : "+f"((D)[0]), "+f"((D)[1]), "+f"((D)[2]), "+f"((D)[3]) \
        : "r"((A)[0]), "r"((A)[1]), "r"((A)[2]), "r"((A)[3]), "r"(b0), "r"(b1))

// ---------- SMEM layout (bytes), M=64 tile ----------
#define O_A0   0
#define O_A1   33792
#define O_PEHI 67584
#define O_DEHI 76800
#define O_BIAS 81920
#define O_DCOL 91648
#define O_WR2  92672
#define SMEM_TOTAL 94208

// ---------- prep kernel: weights -> paired fragment order, fp16 ----------
struct Seg { const float* src; int rs, kv, nv, NT, start; };
struct PrepP { Seg seg[12]; const float* Wout; };

__global__ void prep_kernel(PrepP pp) {
    int b = blockIdx.x * 8 + (threadIdx.x >> 5);
    int l = threadIdx.x & 31;
    if (blockIdx.x == 0) g_dcol[threadIdx.x] = pp.Wout[threadIdx.x * 257 + 256];
    int si = 0;
#pragma unroll
    for (int i = 1; i < 12; i++) if (b >= pp.seg[i].start) si = i;
    Seg sg = pp.seg[si];
    int rel = b - sg.start;
    int s = rel / sg.NT, tg = rel % sg.NT;
    int n = tg * 8 + (l >> 2);
    u64 hv = 0;
#pragma unroll
    for (int idx = 0; idx < 4; idx++) {
        int r = idx >> 1, j = idx & 1;
        int k = s * 16 + (l & 3) * 2 + r * 8 + j;
        float w = (k < sg.kv && n < sg.nv) ? sg.src[(size_t)k * sg.rs + n] : 0.f;
        hv |= (u64)f2h(w) << (16 * idx);
    }
    // paired layout: even/odd blocks interleave per-lane into 16B slots
    g_w[(size_t)(b & ~1) * 32 + (l << 1) + (b & 1)] = hv;
}

// ---------- main kernel ----------
struct Params {
    const float *pos, *dir, *bout, *wr2, *br2;
    const float* bias[10];
    float* out;
};

// MMA over one K-segment, M=64 (2 m-tiles/warp), compile-time trip counts.
template<int NTW, int S, int NT>
__device__ __forceinline__ void run_seg(float (&acc)[2][NTW][4], u32 a_base,
    int strideB, const u64* __restrict__ wseg, int wn, int l)
{
#pragma unroll
    for (int s = 0; s < S; s++) {
        u32 ah[2][4];
        LDMX4(ah[0], a_base + s * 32);
        LDMX4(ah[1], a_base + 16 * strideB + s * 32);
        u64 wh[NTW];
#pragma unroll
        for (int pr = 0; pr < NTW / 2; pr++) {
            ulonglong2 wv = *(const ulonglong2*)(wseg +
                (size_t)(s * NT + wn * NTW + 2 * pr) * 32 + 2 * l);
            wh[2 * pr] = wv.x; wh[2 * pr + 1] = wv.y;
        }
#pragma unroll
        for (int t = 0; t < NTW; t++) {
            u32 h0 = (u32)wh[t], h1 = (u32)(wh[t] >> 32);
            MMA(acc[0][t], ah[0], h0, h1);
            MMA(acc[1][t], ah[1], h0, h1);
        }
    }
}

template<int NTW>
__device__ __forceinline__ void epilogue(float (&acc)[2][NTW][4], u16* HI,
    const float* sbias, bool relu, int wm, int wn, int l)
{
    int cb = wn * NTW * 8 + (l & 3) * 2;
    int rb = wm * 32 + (l >> 2);
#pragma unroll
    for (int mt = 0; mt < 2; mt++)
#pragma unroll
        for (int t = 0; t < NTW; t++)
#pragma unroll
            for (int h = 0; h < 2; h++) {
                int r = rb + mt * 16 + h * 8, c = cb + t * 8;
                float v0 = acc[mt][t][2 * h]     + sbias[c];
                float v1 = acc[mt][t][2 * h + 1] + sbias[c + 1];
                if (relu) { v0 = fmaxf(v0, 0.f); v1 = fmaxf(v1, 0.f); }
                *(u32*)&HI[r * 264 + c] = f2h(v0) | (f2h(v1) << 16);
            }
}

__global__ void __launch_bounds__(256, 2) nerf_mma(Params p)
{
    extern __shared__ char sm[];
    u16* PHI = (u16*)(sm + O_PEHI);
    u16* DHI = (u16*)(sm + O_DEHI);
    float* sball = (float*)(sm + O_BIAS);   // L0..L8 at 256*L, r1 at 2304
    float* sdcol = (float*)(sm + O_DCOL);
    float* swr2  = (float*)(sm + O_WR2);
    float* sred  = (float*)(sm + O_PEHI);   // scratch (PE dead after layer 4)

    const int tid = threadIdx.x;
    const int l = tid & 31, wid = tid >> 5;
    const int wm = wid >> 2, wn = wid & 3;   // 2 m-groups x 4 n-groups

#pragma unroll
    for (int L = 0; L < 9; L++) sball[L * 256 + tid] = p.bias[L][tid];
    if (tid < 128) sball[2304 + tid] = p.bias[9][tid];
    sdcol[tid] = g_dcol[tid];
    for (int i = tid; i < 384; i += 256) swr2[i] = p.wr2[i];

    // posenc (one thread per point, 64 points)
    if (tid < 64) {
        const int m = tid, pt = blockIdx.x * 64 + m;
#define STP(H, STRD, COL, V) (H)[m * STRD + (COL)] = (u16)f2h(V)
        for (int d = 0; d < 3; d++) {
            float x = p.pos[pt * 3 + d];
            STP(PHI, 72, d, x);
            float f = 1.f;
#pragma unroll
            for (int q = 0; q < 10; q++) {
                float s, c; sincosf(x * f, &s, &c);
                STP(PHI, 72, 3 + 6 * q + d, s);
                STP(PHI, 72, 3 + 6 * q + 3 + d, c);
                f *= 2.f;
            }
            float y = p.dir[pt * 3 + d];
            STP(DHI, 40, d, y);
            f = 1.f;
#pragma unroll
            for (int q = 0; q < 4; q++) {
                float s, c; sincosf(y * f, &s, &c);
                STP(DHI, 40, 3 + 6 * q + d, s);
                STP(DHI, 40, 3 + 6 * q + 3 + d, c);
                f *= 2.f;
            }
        }
        STP(PHI, 72, 63, 0.f);
        for (int k = 27; k < 32; k++) STP(DHI, 40, k, 0.f);
#undef STP
    }
    __syncthreads();

    float acc[2][8][4];
#define ZACC() do { _Pragma("unroll") for (int _a = 0; _a < 2; _a++) \
    _Pragma("unroll") for (int _b = 0; _b < 8; _b++) \
    _Pragma("unroll") for (int _c = 0; _c < 4; _c++) acc[_a][_b][_c] = 0.f; } while (0)
#define ABASE(OFF, STRB) (s2u(sm) + (u32)(OFF) + (u32)((wm * 32 + (l & 15)) * (STRB) + (l >> 4) * 16))

    u32 cur = O_A0, nxt = O_A1;

    // layer 0 (pe -> A0); single sync per layer via ping-pong buffers
    ZACC();
    run_seg<8, 4, 32>(acc, ABASE(O_PEHI, 144), 144, g_w + (size_t)SEG_WIN * 32, wn, l);
    epilogue<8>(acc, (u16*)(sm + cur), sball, true, wm, wn, l);
    __syncthreads();

    // hidden layers (Wh5/Wh6 live AFTER the H4PE segment — explicit starts)
    for (int i = 0; i < 7; i++) {
        const int seg_start = (i < 5) ? (SEG_H0 + i * 512) : (SEG_H5 + (i - 5) * 512);
        ZACC();
        run_seg<8, 16, 32>(acc, ABASE(cur, 528), 528, g_w + (size_t)seg_start * 32, wn, l);
        if (i == 4)
            run_seg<8, 4, 32>(acc, ABASE(O_PEHI, 144), 144, g_w + (size_t)SEG_H4PE * 32, wn, l);
        epilogue<8>(acc, (u16*)(sm + nxt), sball + 256 * (1 + i), true, wm, wn, l);
        __syncthreads();
        u32 t = cur; cur = nxt; nxt = t;
    }

    // out layer: density partials (4 threads/point) + features MMA
    {
        const int q = tid >> 6, m = tid & 63;
        float dsum = 0.f;
        const u64* arow = (const u64*)((u16*)(sm + cur) + m * 264 + q * 64);
        const float* dc = sdcol + q * 64;
#pragma unroll
        for (int kb = 0; kb < 16; kb++) {
            u64 v = arow[kb];
            dsum += h2f((u32)(v      ) & 0xFFFF) * dc[kb * 4 + 0];
            dsum += h2f((u32)(v >> 16) & 0xFFFF) * dc[kb * 4 + 1];
            dsum += h2f((u32)(v >> 32) & 0xFFFF) * dc[kb * 4 + 2];
            dsum += h2f((u32)(v >> 48)         ) * dc[kb * 4 + 3];
        }
        sred[tid] = dsum;
    }
    ZACC();
    run_seg<8, 16, 32>(acc, ABASE(cur, 528), 528, g_w + (size_t)SEG_OUT * 32, wn, l);
    epilogue<8>(acc, (u16*)(sm + nxt), sball + 256 * 8, false, wm, wn, l);
    __syncthreads();
    { u32 t = cur; cur = nxt; nxt = t; }
    if (tid < 64)
        p.out[3 * N_PTS + blockIdx.x * 64 + tid] =
            fmaxf(sred[tid] + sred[64 + tid] + sred[128 + tid] + sred[192 + tid]
                  + p.bout[256], 0.f);

    // r1: [features, de] @ Wr1, relu, N=128
    {
        float acc4[2][4][4];
#pragma unroll
        for (int a = 0; a < 2; a++)
#pragma unroll
            for (int b = 0; b < 4; b++)
#pragma unroll
                for (int c = 0; c < 4; c++) acc4[a][b][c] = 0.f;
        run_seg<4, 16, 16>(acc4, ABASE(cur, 528), 528, g_w + (size_t)SEG_R1 * 32, wn, l);
        run_seg<4, 2, 16>(acc4, ABASE(O_DEHI, 80), 80, g_w + (size_t)SEG_R1DE * 32, wn, l);
        epilogue<4>(acc4, (u16*)(sm + nxt), sball + 2304, true, wm, wn, l);
        __syncthreads();
        u32 t = cur; cur = nxt; nxt = t;
    }

    // r2 + sigmoid: 4 threads per point, SMEM reduce
    {
        const int q = tid >> 6, m = tid & 63;
        float r0 = 0.f, r1 = 0.f, r2 = 0.f;
        const u64* arow = (const u64*)((u16*)(sm + cur) + m * 264 + q * 32);
#pragma unroll
        for (int kb = 0; kb < 8; kb++) {
            u64 v = arow[kb];
#pragma unroll
            for (int j = 0; j < 4; j++) {
                float hv = h2f((u32)(v >> (16 * j)) & 0xFFFF);
                const float* w = swr2 + (q * 32 + kb * 4 + j) * 3;
                r0 += hv * w[0]; r1 += hv * w[1]; r2 += hv * w[2];
            }
        }
        sred[tid] = r0; sred[256 + tid] = r1; sred[512 + tid] = r2;
    }
    __syncthreads();
    if (tid < 64) {
        const int pt = blockIdx.x * 64 + tid;
        float r0 = sred[tid] + sred[64 + tid] + sred[128 + tid] + sred[192 + tid] + p.br2[0];
        float r1 = sred[256 + tid] + sred[320 + tid] + sred[384 + tid] + sred[448 + tid] + p.br2[1];
        float r2 = sred[512 + tid] + sred[576 + tid] + sred[640 + tid] + sred[704 + tid] + p.br2[2];
        p.out[pt * 3 + 0] = 1.f / (1.f + expf(-r0));
        p.out[pt * 3 + 1] = 1.f / (1.f + expf(-r1));
        p.out[pt * 3 + 2] = 1.f / (1.f + expf(-r2));
    }
}

// ---------- host ----------
extern "C" void kernel_launch(void* const* d_in, const int* in_sizes, int n_in,
                              void* d_out, int out_size)
{
    const float* pos  = (const float*)d_in[0];
    const float* dir  = (const float*)d_in[1];
    const float* Win  = (const float*)d_in[2];
    const float* bin  = (const float*)d_in[3];
    const float* Wh[7]; const float* bh[7];
    for (int i = 0; i < 7; i++) { Wh[i] = (const float*)d_in[4 + 2 * i]; bh[i] = (const float*)d_in[5 + 2 * i]; }
    const float* Wout = (const float*)d_in[18];
    const float* bout = (const float*)d_in[19];
    const float* Wr1  = (const float*)d_in[20];
    const float* br1  = (const float*)d_in[21];
    const float* Wr2  = (const float*)d_in[22];
    const float* br2  = (const float*)d_in[23];

    static PrepP pp;
    pp.seg[0]  = { Win,               256, 63,  256, 32, SEG_WIN };
    for (int i = 0; i < 5; i++)
        pp.seg[1 + i] = { Wh[i],      256, 256, 256, 32, SEG_H0 + i * 512 };
    pp.seg[6]  = { Wh[4] + 256 * 256, 256, 63,  256, 32, SEG_H4PE };
    pp.seg[7]  = { Wh[5],             256, 256, 256, 32, SEG_H5 };
    pp.seg[8]  = { Wh[6],             256, 256, 256, 32, SEG_H6 };
    pp.seg[9]  = { Wout,              257, 256, 256, 32, SEG_OUT };
    pp.seg[10] = { Wr1,               128, 256, 128, 16, SEG_R1 };
    pp.seg[11] = { Wr1 + 256 * 128,   128, 27,  128, 16, SEG_R1DE };
    pp.Wout = Wout;

    static Params p;
    p.pos = pos; p.dir = dir; p.bout = bout; p.wr2 = Wr2; p.br2 = br2;
    p.bias[0] = bin;
    for (int i = 0; i < 7; i++) p.bias[1 + i] = bh[i];
    p.bias[8] = bout; p.bias[9] = br1;
    p.out = (float*)d_out;

    prep_kernel<<<TOTB / 8, 256>>>(pp);
    cudaFuncSetAttribute(nerf_mma, cudaFuncAttributeMaxDynamicSharedMemorySize, SMEM_TOTAL);
    nerf_mma<<<N_PTS / 64, 256, SMEM_TOTAL>>>(p);
}

// round 13
// speedup vs baseline: 1.3682x; 1.0409x over previous
#include <cuda_runtime.h>
#include <cuda_fp16.h>
#include <stdint.h>
#include <math.h>

typedef uint32_t u32; typedef uint64_t u64; typedef unsigned short u16;

#define N_PTS 262144
#define TOTB 4640

// weight blocks, PAIRED fragment order: for even b, lanes hold
// [ (b>>1)*64 + 2l ] = block b, [ +1 ] = block b+1  (16B/lane -> LDG.128)
__device__ __align__(16) u64 g_w[TOTB * 32];
__device__ float g_dcol[256];

// seg block offsets (layout: Win | Wh0..Wh4 | H4PE | Wh5 | Wh6 | Wout | Wr1 | Wr1de)
#define SEG_WIN  0
#define SEG_H0   128
#define SEG_H4PE 2688
#define SEG_H5   2816
#define SEG_H6   3328
#define SEG_OUT  3840
#define SEG_R1   4352
#define SEG_R1DE 4608

__device__ __forceinline__ u32 f2h(float f) {
    return (u32)__half_as_ushort(__float2half_rn(f));
}
__device__ __forceinline__ float h2f(u32 h) {
    return __half2float(__ushort_as_half((u16)h));
}
// packed: lo half = a, hi half = b
__device__ __forceinline__ u32 f2h2(float a, float b) {
    u32 r; asm("cvt.rn.f16x2.f32 %0, %1, %2;" : "=r"(r) : "f"(b), "f"(a)); return r;
}
__device__ __forceinline__ u32 s2u(const void* p) {
    u32 a;
    asm("{ .reg .u64 t; cvta.to.shared.u64 t, %1; cvt.u32.u64 %0, t; }" : "=r"(a) : "l"(p));
    return a;
}

#define LDMX4(R, addr) \
    asm volatile("ldmatrix.sync.aligned.m8n8.x4.shared.b16 {%0,%1,%2,%3}, [%4];" \
        : "=r"((R)[0]), "=r"((R)[1]), "=r"((R)[2]), "=r"((R)[3]) : "r"(addr))

#define MMA(D, A, b0, b1) \
    asm volatile("mma.sync.aligned.m16n8k16.row.col.f32.f16.f16.f32 " \
        "{%0,%1,%2,%3},{%4,%5,%6,%7},{%8,%9},{%0,%1,%2,%3};" \
        : "+f"((D)[0]), "+f"((D)[1]), "+f"((D)[2]), "+f"((D)[3]) \
        : "r"((A)[0]), "r"((A)[1]), "r"((A)[2]), "r"((A)[3]), "r"(b0), "r"(b1))

// ---------- SMEM layout (bytes), M=32 tile, 4 CTAs/SM ----------
#define O_A0   0            // 32 rows x 264 u16 = 16896
#define O_A1   16896
#define O_PE   33792        // 32 x 72 u16 = 4608
#define O_DE   38400        // 32 x 40 u16 = 2560
#define O_BIAS 40960        // 2432 floats = 9728
#define O_DCOL 50688        // 1024
#define O_WR2  51712        // 1536
#define SMEM_TOTAL 53248

// ---------- prep kernel: weights -> paired fragment order, fp16 ----------
struct Seg { const float* src; int rs, kv, nv, NT, start; };
struct PrepP { Seg seg[12]; const float* Wout; };

__global__ void prep_kernel(PrepP pp) {
    int b = blockIdx.x * 8 + (threadIdx.x >> 5);
    int l = threadIdx.x & 31;
    if (blockIdx.x == 0) g_dcol[threadIdx.x] = pp.Wout[threadIdx.x * 257 + 256];
    int si = 0;
#pragma unroll
    for (int i = 1; i < 12; i++) if (b >= pp.seg[i].start) si = i;
    Seg sg = pp.seg[si];
    int rel = b - sg.start;
    int s = rel / sg.NT, tg = rel % sg.NT;
    int n = tg * 8 + (l >> 2);
    u64 hv = 0;
#pragma unroll
    for (int idx = 0; idx < 4; idx++) {
        int r = idx >> 1, j = idx & 1;
        int k = s * 16 + (l & 3) * 2 + r * 8 + j;
        float w = (k < sg.kv && n < sg.nv) ? sg.src[(size_t)k * sg.rs + n] : 0.f;
        hv |= (u64)f2h(w) << (16 * idx);
    }
    g_w[(size_t)(b & ~1) * 32 + (l << 1) + (b & 1)] = hv;
}

// ---------- main kernel ----------
struct Params {
    const float *pos, *dir, *bout, *wr2, *br2;
    const float* bias[10];
    float* out;
};

// MMA over one K-segment, M=32 (2 m-tiles/warp), compile-time trip counts.
template<int NTW, int S, int NT>
__device__ __forceinline__ void run_seg(float (&acc)[2][NTW][4], u32 a_base,
    int strideB, const u64* __restrict__ wseg, int wn, int l)
{
#pragma unroll
    for (int s = 0; s < S; s++) {
        u32 ah[2][4];
        LDMX4(ah[0], a_base + s * 32);
        LDMX4(ah[1], a_base + 16 * strideB + s * 32);
        u64 wh[NTW];
#pragma unroll
        for (int pr = 0; pr < NTW / 2; pr++) {
            ulonglong2 wv = *(const ulonglong2*)(wseg +
                (size_t)(s * NT + wn * NTW + 2 * pr) * 32 + 2 * l);
            wh[2 * pr] = wv.x; wh[2 * pr + 1] = wv.y;
        }
#pragma unroll
        for (int t = 0; t < NTW; t++) {
            u32 h0 = (u32)wh[t], h1 = (u32)(wh[t] >> 32);
            MMA(acc[0][t], ah[0], h0, h1);
            MMA(acc[1][t], ah[1], h0, h1);
        }
    }
}

template<int NTW>
__device__ __forceinline__ void epilogue(float (&acc)[2][NTW][4], u16* HI,
    const float* sbias, bool relu, int wn, int l)
{
    int cb = wn * NTW * 8 + (l & 3) * 2;
    int rb = l >> 2;
#pragma unroll
    for (int mt = 0; mt < 2; mt++)
#pragma unroll
        for (int t = 0; t < NTW; t++)
#pragma unroll
            for (int h = 0; h < 2; h++) {
                int r = rb + mt * 16 + h * 8, c = cb + t * 8;
                float v0 = acc[mt][t][2 * h]     + sbias[c];
                float v1 = acc[mt][t][2 * h + 1] + sbias[c + 1];
                if (relu) { v0 = fmaxf(v0, 0.f); v1 = fmaxf(v1, 0.f); }
                *(u32*)&HI[r * 264 + c] = f2h2(v0, v1);
            }
}

__global__ void __launch_bounds__(128, 4) nerf_mma(Params p)
{
    extern __shared__ char sm[];
    u16* PHI = (u16*)(sm + O_PE);
    u16* DHI = (u16*)(sm + O_DE);
    float* sball = (float*)(sm + O_BIAS);   // L0..L8 at 256*L, r1 at 2304
    float* sdcol = (float*)(sm + O_DCOL);
    float* swr2  = (float*)(sm + O_WR2);
    float* sred  = (float*)(sm + O_PE);     // scratch (PE dead after layer 4)

    const int tid = threadIdx.x;
    const int l = tid & 31, wn = tid >> 5;   // 4 warps, each a 64-col group

#pragma unroll
    for (int L = 0; L < 9; L++) {
        sball[L * 256 + tid]       = p.bias[L][tid];
        sball[L * 256 + 128 + tid] = p.bias[L][128 + tid];
    }
    sball[2304 + tid] = p.bias[9][tid];
    sdcol[tid] = g_dcol[tid]; sdcol[128 + tid] = g_dcol[128 + tid];
    for (int i = tid; i < 384; i += 128) swr2[i] = p.wr2[i];

    // posenc (one thread per point, 32 points)
    if (tid < 32) {
        const int m = tid, pt = blockIdx.x * 32 + m;
#define STP(H, STRD, COL, V) (H)[m * STRD + (COL)] = (u16)f2h(V)
        for (int d = 0; d < 3; d++) {
            float x = p.pos[pt * 3 + d];
            STP(PHI, 72, d, x);
            float f = 1.f;
#pragma unroll
            for (int q = 0; q < 10; q++) {
                float s, c; sincosf(x * f, &s, &c);
                STP(PHI, 72, 3 + 6 * q + d, s);
                STP(PHI, 72, 3 + 6 * q + 3 + d, c);
                f *= 2.f;
            }
            float y = p.dir[pt * 3 + d];
            STP(DHI, 40, d, y);
            f = 1.f;
#pragma unroll
            for (int q = 0; q < 4; q++) {
                float s, c; sincosf(y * f, &s, &c);
                STP(DHI, 40, 3 + 6 * q + d, s);
                STP(DHI, 40, 3 + 6 * q + 3 + d, c);
                f *= 2.f;
            }
        }
        STP(PHI, 72, 63, 0.f);
        for (int k = 27; k < 32; k++) STP(DHI, 40, k, 0.f);
#undef STP
    }
    __syncthreads();

    float acc[2][8][4];
#define ZACC() do { _Pragma("unroll") for (int _a = 0; _a < 2; _a++) \
    _Pragma("unroll") for (int _b = 0; _b < 8; _b++) \
    _Pragma("unroll") for (int _c = 0; _c < 4; _c++) acc[_a][_b][_c] = 0.f; } while (0)
    const u32 lane_a  = (u32)((l & 15) * 528 + (l >> 4) * 16);
    const u32 lane_pe = (u32)((l & 15) * 144 + (l >> 4) * 16);
    const u32 lane_de = (u32)((l & 15) * 80  + (l >> 4) * 16);
    const u32 sb = s2u(sm);

    u32 cur = O_A0, nxt = O_A1;

    // layer 0 (pe -> A0); single sync per layer via ping-pong buffers
    ZACC();
    run_seg<8, 4, 32>(acc, sb + O_PE + lane_pe, 144, g_w + (size_t)SEG_WIN * 32, wn, l);
    epilogue<8>(acc, (u16*)(sm + cur), sball, true, wn, l);
    __syncthreads();

    // hidden layers (Wh5/Wh6 live AFTER the H4PE segment — explicit starts)
    for (int i = 0; i < 7; i++) {
        const int seg_start = (i < 5) ? (SEG_H0 + i * 512) : (SEG_H5 + (i - 5) * 512);
        ZACC();
        run_seg<8, 16, 32>(acc, sb + cur + lane_a, 528, g_w + (size_t)seg_start * 32, wn, l);
        if (i == 4)
            run_seg<8, 4, 32>(acc, sb + O_PE + lane_pe, 144, g_w + (size_t)SEG_H4PE * 32, wn, l);
        epilogue<8>(acc, (u16*)(sm + nxt), sball + 256 * (1 + i), true, wn, l);
        __syncthreads();
        u32 t = cur; cur = nxt; nxt = t;
    }

    // out layer: density partials (4 threads/point) + features MMA
    {
        const int q = tid >> 5, m = tid & 31;
        float dsum = 0.f;
        const u64* arow = (const u64*)((u16*)(sm + cur) + m * 264 + q * 64);
        const float* dc = sdcol + q * 64;
#pragma unroll
        for (int kb = 0; kb < 16; kb++) {
            u64 v = arow[kb];
            dsum += h2f((u32)(v      ) & 0xFFFF) * dc[kb * 4 + 0];
            dsum += h2f((u32)(v >> 16) & 0xFFFF) * dc[kb * 4 + 1];
            dsum += h2f((u32)(v >> 32) & 0xFFFF) * dc[kb * 4 + 2];
            dsum += h2f((u32)(v >> 48)         ) * dc[kb * 4 + 3];
        }
        sred[tid] = dsum;
    }
    ZACC();
    run_seg<8, 16, 32>(acc, sb + cur + lane_a, 528, g_w + (size_t)SEG_OUT * 32, wn, l);
    epilogue<8>(acc, (u16*)(sm + nxt), sball + 256 * 8, false, wn, l);
    __syncthreads();
    { u32 t = cur; cur = nxt; nxt = t; }
    if (tid < 32)
        p.out[3 * N_PTS + blockIdx.x * 32 + tid] =
            fmaxf(sred[tid] + sred[32 + tid] + sred[64 + tid] + sred[96 + tid]
                  + p.bout[256], 0.f);

    // r1: [features, de] @ Wr1, relu, N=128 (each warp n=32)
    {
        float acc4[2][4][4];
#pragma unroll
        for (int a = 0; a < 2; a++)
#pragma unroll
            for (int b = 0; b < 4; b++)
#pragma unroll
                for (int c = 0; c < 4; c++) acc4[a][b][c] = 0.f;
        run_seg<4, 16, 16>(acc4, sb + cur + lane_a, 528, g_w + (size_t)SEG_R1 * 32, wn, l);
        run_seg<4, 2, 16>(acc4, sb + O_DE + lane_de, 80, g_w + (size_t)SEG_R1DE * 32, wn, l);
        epilogue<4>(acc4, (u16*)(sm + nxt), sball + 2304, true, wn, l);
        __syncthreads();
        u32 t = cur; cur = nxt; nxt = t;
    }

    // r2 + sigmoid: 4 threads per point (32 cols each), SMEM reduce
    {
        const int q = tid >> 5, m = tid & 31;
        float r0 = 0.f, r1 = 0.f, r2 = 0.f;
        const u64* arow = (const u64*)((u16*)(sm + cur) + m * 264 + q * 32);
#pragma unroll
        for (int kb = 0; kb < 8; kb++) {
            u64 v = arow[kb];
#pragma unroll
            for (int j = 0; j < 4; j++) {
                float hv = h2f((u32)(v >> (16 * j)) & 0xFFFF);
                const float* w = swr2 + (q * 32 + kb * 4 + j) * 3;
                r0 += hv * w[0]; r1 += hv * w[1]; r2 += hv * w[2];
            }
        }
        sred[tid] = r0; sred[128 + tid] = r1; sred[256 + tid] = r2;
    }
    __syncthreads();
    if (tid < 32) {
        const int pt = blockIdx.x * 32 + tid;
        float r0 = sred[tid] + sred[32 + tid] + sred[64 + tid] + sred[96 + tid] + p.br2[0];
        float r1 = sred[128 + tid] + sred[160 + tid] + sred[192 + tid] + sred[224 + tid] + p.br2[1];
        float r2 = sred[256 + tid] + sred[288 + tid] + sred[320 + tid] + sred[352 + tid] + p.br2[2];
        p.out[pt * 3 + 0] = 1.f / (1.f + expf(-r0));
        p.out[pt * 3 + 1] = 1.f / (1.f + expf(-r1));
        p.out[pt * 3 + 2] = 1.f / (1.f + expf(-r2));
    }
}

// ---------- host ----------
extern "C" void kernel_launch(void* const* d_in, const int* in_sizes, int n_in,
                              void* d_out, int out_size)
{
    const float* pos  = (const float*)d_in[0];
    const float* dir  = (const float*)d_in[1];
    const float* Win  = (const float*)d_in[2];
    const float* bin  = (const float*)d_in[3];
    const float* Wh[7]; const float* bh[7];
    for (int i = 0; i < 7; i++) { Wh[i] = (const float*)d_in[4 + 2 * i]; bh[i] = (const float*)d_in[5 + 2 * i]; }
    const float* Wout = (const float*)d_in[18];
    const float* bout = (const float*)d_in[19];
    const float* Wr1  = (const float*)d_in[20];
    const float* br1  = (const float*)d_in[21];
    const float* Wr2  = (const float*)d_in[22];
    const float* br2  = (const float*)d_in[23];

    static PrepP pp;
    pp.seg[0]  = { Win,               256, 63,  256, 32, SEG_WIN };
    for (int i = 0; i < 5; i++)
        pp.seg[1 + i] = { Wh[i],      256, 256, 256, 32, SEG_H0 + i * 512 };
    pp.seg[6]  = { Wh[4] + 256 * 256, 256, 63,  256, 32, SEG_H4PE };
    pp.seg[7]  = { Wh[5],             256, 256, 256, 32, SEG_H5 };
    pp.seg[8]  = { Wh[6],             256, 256, 256, 32, SEG_H6 };
    pp.seg[9]  = { Wout,              257, 256, 256, 32, SEG_OUT };
    pp.seg[10] = { Wr1,               128, 256, 128, 16, SEG_R1 };
    pp.seg[11] = { Wr1 + 256 * 128,   128, 27,  128, 16, SEG_R1DE };
    pp.Wout = Wout;

    static Params p;
    p.pos = pos; p.dir = dir; p.bout = bout; p.wr2 = Wr2; p.br2 = br2;
    p.bias[0] = bin;
    for (int i = 0; i < 7; i++) p.bias[1 + i] = bh[i];
    p.bias[8] = bout; p.bias[9] = br1;
    p.out = (float*)d_out;

    prep_kernel<<<TOTB / 8, 256>>>(pp);
    cudaFuncSetAttribute(nerf_mma, cudaFuncAttributeMaxDynamicSharedMemorySize, SMEM_TOTAL);
    nerf_mma<<<N_PTS / 32, 128, SMEM_TOTAL>>>(p);
}

// round 14
// speedup vs baseline: 1.4264x; 1.0425x over previous
#include <cuda_runtime.h>
#include <cuda_fp16.h>
#include <stdint.h>
#include <math.h>

typedef uint32_t u32; typedef uint64_t u64; typedef unsigned short u16;

#define N_PTS 262144
#define TOTB 4640

// weight blocks, PAIRED fragment order: for even b, lanes hold
// [ (b>>1)*64 + 2l ] = block b, [ +1 ] = block b+1  (16B/lane -> LDG.128)
__device__ __align__(16) u64 g_w[TOTB * 32];
__device__ float g_dcol[256];

// seg block offsets (layout: Win | Wh0..Wh4 | H4PE | Wh5 | Wh6 | Wout | Wr1 | Wr1de)
#define SEG_WIN  0
#define SEG_H0   128
#define SEG_H4PE 2688
#define SEG_H5   2816
#define SEG_H6   3328
#define SEG_OUT  3840
#define SEG_R1   4352
#define SEG_R1DE 4608

__device__ __forceinline__ u32 f2h(float f) {
    return (u32)__half_as_ushort(__float2half_rn(f));
}
__device__ __forceinline__ float h2f(u32 h) {
    return __half2float(__ushort_as_half((u16)h));
}
// packed: lo half = a, hi half = b
__device__ __forceinline__ u32 f2h2(float a, float b) {
    u32 r; asm("cvt.rn.f16x2.f32 %0, %1, %2;" : "=r"(r) : "f"(b), "f"(a)); return r;
}
__device__ __forceinline__ u32 s2u(const void* p) {
    u32 a;
    asm("{ .reg .u64 t; cvta.to.shared.u64 t, %1; cvt.u32.u64 %0, t; }" : "=r"(a) : "l"(p));
    return a;
}

#define LDMX4(R, addr) \
    asm volatile("ldmatrix.sync.aligned.m8n8.x4.shared.b16 {%0,%1,%2,%3}, [%4];" \
        : "=r"((R)[0]), "=r"((R)[1]), "=r"((R)[2]), "=r"((R)[3]) : "r"(addr))

#define MMA(D, A, b0, b1) \
    asm volatile("mma.sync.aligned.m16n8k16.row.col.f32.f16.f16.f32 " \
        "{%0,%1,%2,%3},{%4,%5,%6,%7},{%8,%9},{%0,%1,%2,%3};" \
        : "+f"((D)[0]), "+f"((D)[1]), "+f"((D)[2]), "+f"((D)[3]) \
        : "r"((A)[0]), "r"((A)[1]), "r"((A)[2]), "r"((A)[3]), "r"(b0), "r"(b1))

// ---------- SMEM layout (bytes), M=32 tile, 5 CTAs/SM ----------
#define O_A0   0            // 32 rows x 264 u16 = 16896
#define O_A1   16896
#define O_PE   33792        // 32 x 72 u16 = 4608 (reused as sred scratch later)
#define O_DE   38400        // 32 x 40 u16 = 2560
#define O_DCOL 40960        // 1024
#define O_WR2  41984        // 1536
#define SMEM_TOTAL 43520

// ---------- prep kernel: weights -> paired fragment order, fp16 ----------
struct Seg { const float* src; int rs, kv, nv, NT, start; };
struct PrepP { Seg seg[12]; const float* Wout; };

__global__ void prep_kernel(PrepP pp) {
    int b = blockIdx.x * 8 + (threadIdx.x >> 5);
    int l = threadIdx.x & 31;
    if (blockIdx.x == 0) g_dcol[threadIdx.x] = pp.Wout[threadIdx.x * 257 + 256];
    int si = 0;
#pragma unroll
    for (int i = 1; i < 12; i++) if (b >= pp.seg[i].start) si = i;
    Seg sg = pp.seg[si];
    int rel = b - sg.start;
    int s = rel / sg.NT, tg = rel % sg.NT;
    int n = tg * 8 + (l >> 2);
    u64 hv = 0;
#pragma unroll
    for (int idx = 0; idx < 4; idx++) {
        int r = idx >> 1, j = idx & 1;
        int k = s * 16 + (l & 3) * 2 + r * 8 + j;
        float w = (k < sg.kv && n < sg.nv) ? sg.src[(size_t)k * sg.rs + n] : 0.f;
        hv |= (u64)f2h(w) << (16 * idx);
    }
    g_w[(size_t)(b & ~1) * 32 + (l << 1) + (b & 1)] = hv;
}

// ---------- main kernel ----------
struct Params {
    const float *pos, *dir, *bout, *wr2, *br2;
    const float* bias[10];
    float* out;
};

// MMA over one K-segment, M=32 (2 m-tiles/warp), compile-time trip counts.
// Weight loads split into 2 half-batches to cap live registers (5 CTAs/SM -> 102 regs).
template<int NTW, int S, int NT>
__device__ __forceinline__ void run_seg(float (&acc)[2][NTW][4], u32 a_base,
    int strideB, const u64* __restrict__ wseg, int wn, int l)
{
#pragma unroll
    for (int s = 0; s < S; s++) {
        u32 ah[2][4];
        LDMX4(ah[0], a_base + s * 32);
        LDMX4(ah[1], a_base + 16 * strideB + s * 32);
        const u64* wbase = wseg + (size_t)(s * NT + wn * NTW) * 32 + 2 * l;
#pragma unroll
        for (int half = 0; half < (NTW + 3) / 4; half++) {
            u64 wh[4];
#pragma unroll
            for (int pr = 0; pr < 2; pr++) {
                if (half * 2 + pr < NTW / 2) {
                    ulonglong2 wv = *(const ulonglong2*)(wbase + (size_t)(half * 4 + 2 * pr) * 32);
                    wh[2 * pr] = wv.x; wh[2 * pr + 1] = wv.y;
                }
            }
#pragma unroll
            for (int j = 0; j < 4; j++) {
                int t = half * 4 + j;
                if (t < NTW) {
                    u32 h0 = (u32)wh[j], h1 = (u32)(wh[j] >> 32);
                    MMA(acc[0][t], ah[0], h0, h1);
                    MMA(acc[1][t], ah[1], h0, h1);
                }
            }
        }
    }
}

// epilogue: bias straight from global (L1-hot), no SMEM table
template<int NTW>
__device__ __forceinline__ void epilogue(float (&acc)[2][NTW][4], u16* HI,
    const float* __restrict__ gbias, bool relu, int wn, int l)
{
    int cb = wn * NTW * 8 + (l & 3) * 2;
    int rb = l >> 2;
#pragma unroll
    for (int t = 0; t < NTW; t++) {
        int c = cb + t * 8;
        float2 bv = __ldg((const float2*)(gbias + c));
#pragma unroll
        for (int mt = 0; mt < 2; mt++)
#pragma unroll
            for (int h = 0; h < 2; h++) {
                int r = rb + mt * 16 + h * 8;
                float v0 = acc[mt][t][2 * h]     + bv.x;
                float v1 = acc[mt][t][2 * h + 1] + bv.y;
                if (relu) { v0 = fmaxf(v0, 0.f); v1 = fmaxf(v1, 0.f); }
                *(u32*)&HI[r * 264 + c] = f2h2(v0, v1);
            }
    }
}

__global__ void __launch_bounds__(128, 5) nerf_mma(Params p)
{
    extern __shared__ char sm[];
    u16* PHI = (u16*)(sm + O_PE);
    u16* DHI = (u16*)(sm + O_DE);
    float* sdcol = (float*)(sm + O_DCOL);
    float* swr2  = (float*)(sm + O_WR2);
    float* sred  = (float*)(sm + O_PE);     // scratch (PE dead after layer 4)

    const int tid = threadIdx.x;
    const int l = tid & 31, wn = tid >> 5;   // 4 warps, each a 64-col group

    sdcol[tid] = g_dcol[tid]; sdcol[128 + tid] = g_dcol[128 + tid];
    for (int i = tid; i < 384; i += 128) swr2[i] = p.wr2[i];

    // posenc (one thread per point, 32 points)
    if (tid < 32) {
        const int m = tid, pt = blockIdx.x * 32 + m;
#define STP(H, STRD, COL, V) (H)[m * STRD + (COL)] = (u16)f2h(V)
        for (int d = 0; d < 3; d++) {
            float x = p.pos[pt * 3 + d];
            STP(PHI, 72, d, x);
            float f = 1.f;
#pragma unroll
            for (int q = 0; q < 10; q++) {
                float s, c; sincosf(x * f, &s, &c);
                STP(PHI, 72, 3 + 6 * q + d, s);
                STP(PHI, 72, 3 + 6 * q + 3 + d, c);
                f *= 2.f;
            }
            float y = p.dir[pt * 3 + d];
            STP(DHI, 40, d, y);
            f = 1.f;
#pragma unroll
            for (int q = 0; q < 4; q++) {
                float s, c; sincosf(y * f, &s, &c);
                STP(DHI, 40, 3 + 6 * q + d, s);
                STP(DHI, 40, 3 + 6 * q + 3 + d, c);
                f *= 2.f;
            }
        }
        STP(PHI, 72, 63, 0.f);
        for (int k = 27; k < 32; k++) STP(DHI, 40, k, 0.f);
#undef STP
    }
    __syncthreads();

    float acc[2][8][4];
#define ZACC() do { _Pragma("unroll") for (int _a = 0; _a < 2; _a++) \
    _Pragma("unroll") for (int _b = 0; _b < 8; _b++) \
    _Pragma("unroll") for (int _c = 0; _c < 4; _c++) acc[_a][_b][_c] = 0.f; } while (0)
    const u32 lane_a  = (u32)((l & 15) * 528 + (l >> 4) * 16);
    const u32 lane_pe = (u32)((l & 15) * 144 + (l >> 4) * 16);
    const u32 lane_de = (u32)((l & 15) * 80  + (l >> 4) * 16);
    const u32 sb = s2u(sm);

    u32 cur = O_A0, nxt = O_A1;

    // layer 0 (pe -> A0); single sync per layer via ping-pong buffers
    ZACC();
    run_seg<8, 4, 32>(acc, sb + O_PE + lane_pe, 144, g_w + (size_t)SEG_WIN * 32, wn, l);
    epilogue<8>(acc, (u16*)(sm + cur), p.bias[0], true, wn, l);
    __syncthreads();

    // hidden layers (Wh5/Wh6 live AFTER the H4PE segment — explicit starts)
    for (int i = 0; i < 7; i++) {
        const int seg_start = (i < 5) ? (SEG_H0 + i * 512) : (SEG_H5 + (i - 5) * 512);
        ZACC();
        run_seg<8, 16, 32>(acc, sb + cur + lane_a, 528, g_w + (size_t)seg_start * 32, wn, l);
        if (i == 4)
            run_seg<8, 4, 32>(acc, sb + O_PE + lane_pe, 144, g_w + (size_t)SEG_H4PE * 32, wn, l);
        epilogue<8>(acc, (u16*)(sm + nxt), p.bias[1 + i], true, wn, l);
        __syncthreads();
        u32 t = cur; cur = nxt; nxt = t;
    }

    // out layer: density partials (4 threads/point) + features MMA
    {
        const int q = tid >> 5, m = tid & 31;
        float dsum = 0.f;
        const u64* arow = (const u64*)((u16*)(sm + cur) + m * 264 + q * 64);
        const float* dc = sdcol + q * 64;
#pragma unroll
        for (int kb = 0; kb < 16; kb++) {
            u64 v = arow[kb];
            dsum += h2f((u32)(v      ) & 0xFFFF) * dc[kb * 4 + 0];
            dsum += h2f((u32)(v >> 16) & 0xFFFF) * dc[kb * 4 + 1];
            dsum += h2f((u32)(v >> 32) & 0xFFFF) * dc[kb * 4 + 2];
            dsum += h2f((u32)(v >> 48)         ) * dc[kb * 4 + 3];
        }
        sred[tid] = dsum;
    }
    ZACC();
    run_seg<8, 16, 32>(acc, sb + cur + lane_a, 528, g_w + (size_t)SEG_OUT * 32, wn, l);
    epilogue<8>(acc, (u16*)(sm + nxt), p.bias[8], false, wn, l);
    __syncthreads();
    { u32 t = cur; cur = nxt; nxt = t; }
    if (tid < 32)
        p.out[3 * N_PTS + blockIdx.x * 32 + tid] =
            fmaxf(sred[tid] + sred[32 + tid] + sred[64 + tid] + sred[96 + tid]
                  + p.bout[256], 0.f);

    // r1: [features, de] @ Wr1, relu, N=128 (each warp n=32)
    {
        float acc4[2][4][4];
#pragma unroll
        for (int a = 0; a < 2; a++)
#pragma unroll
            for (int b = 0; b < 4; b++)
#pragma unroll
                for (int c = 0; c < 4; c++) acc4[a][b][c] = 0.f;
        run_seg<4, 16, 16>(acc4, sb + cur + lane_a, 528, g_w + (size_t)SEG_R1 * 32, wn, l);
        run_seg<4, 2, 16>(acc4, sb + O_DE + lane_de, 80, g_w + (size_t)SEG_R1DE * 32, wn, l);
        epilogue<4>(acc4, (u16*)(sm + nxt), p.bias[9], true, wn, l);
        __syncthreads();
        u32 t = cur; cur = nxt; nxt = t;
    }

    // r2 + sigmoid: 4 threads per point (32 cols each), SMEM reduce
    {
        const int q = tid >> 5, m = tid & 31;
        float r0 = 0.f, r1 = 0.f, r2 = 0.f;
        const u64* arow = (const u64*)((u16*)(sm + cur) + m * 264 + q * 32);
#pragma unroll
        for (int kb = 0; kb < 8; kb++) {
            u64 v = arow[kb];
#pragma unroll
            for (int j = 0; j < 4; j++) {
                float hv = h2f((u32)(v >> (16 * j)) & 0xFFFF);
                const float* w = swr2 + (q * 32 + kb * 4 + j) * 3;
                r0 += hv * w[0]; r1 += hv * w[1]; r2 += hv * w[2];
            }
        }
        sred[tid] = r0; sred[128 + tid] = r1; sred[256 + tid] = r2;
    }
    __syncthreads();
    if (tid < 32) {
        const int pt = blockIdx.x * 32 + tid;
        float r0 = sred[tid] + sred[32 + tid] + sred[64 + tid] + sred[96 + tid] + p.br2[0];
        float r1 = sred[128 + tid] + sred[160 + tid] + sred[192 + tid] + sred[224 + tid] + p.br2[1];
        float r2 = sred[256 + tid] + sred[288 + tid] + sred[320 + tid] + sred[352 + tid] + p.br2[2];
        p.out[pt * 3 + 0] = 1.f / (1.f + expf(-r0));
        p.out[pt * 3 + 1] = 1.f / (1.f + expf(-r1));
        p.out[pt * 3 + 2] = 1.f / (1.f + expf(-r2));
    }
}

// ---------- host ----------
extern "C" void kernel_launch(void* const* d_in, const int* in_sizes, int n_in,
                              void* d_out, int out_size)
{
    const float* pos  = (const float*)d_in[0];
    const float* dir  = (const float*)d_in[1];
    const float* Win  = (const float*)d_in[2];
    const float* bin  = (const float*)d_in[3];
    const float* Wh[7]; const float* bh[7];
    for (int i = 0; i < 7; i++) { Wh[i] = (const float*)d_in[4 + 2 * i]; bh[i] = (const float*)d_in[5 + 2 * i]; }
    const float* Wout = (const float*)d_in[18];
    const float* bout = (const float*)d_in[19];
    const float* Wr1  = (const float*)d_in[20];
    const float* br1  = (const float*)d_in[21];
    const float* Wr2  = (const float*)d_in[22];
    const float* br2  = (const float*)d_in[23];

    static PrepP pp;
    pp.seg[0]  = { Win,               256, 63,  256, 32, SEG_WIN };
    for (int i = 0; i < 5; i++)
        pp.seg[1 + i] = { Wh[i],      256, 256, 256, 32, SEG_H0 + i * 512 };
    pp.seg[6]  = { Wh[4] + 256 * 256, 256, 63,  256, 32, SEG_H4PE };
    pp.seg[7]  = { Wh[5],             256, 256, 256, 32, SEG_H5 };
    pp.seg[8]  = { Wh[6],             256, 256, 256, 32, SEG_H6 };
    pp.seg[9]  = { Wout,              257, 256, 256, 32, SEG_OUT };
    pp.seg[10] = { Wr1,               128, 256, 128, 16, SEG_R1 };
    pp.seg[11] = { Wr1 + 256 * 128,   128, 27,  128, 16, SEG_R1DE };
    pp.Wout = Wout;

    static Params p;
    p.pos = pos; p.dir = dir; p.bout = bout; p.wr2 = Wr2; p.br2 = br2;
    p.bias[0] = bin;
    for (int i = 0; i < 7; i++) p.bias[1 + i] = bh[i];
    p.bias[8] = bout; p.bias[9] = br1;
    p.out = (float*)d_out;

    prep_kernel<<<TOTB / 8, 256>>>(pp);
    cudaFuncSetAttribute(nerf_mma, cudaFuncAttributeMaxDynamicSharedMemorySize, SMEM_TOTAL);
    nerf_mma<<<N_PTS / 32, 128, SMEM_TOTAL>>>(p);
}